// round 12
// baseline (speedup 1.0000x reference)
#include <cuda_runtime.h>
#include <cuda_bf16.h>
#include <float.h>

// Problem: out[b][c] = max over (h,w) of in[b][h][w][c]
//   in : [32, 224, 224, 128] f32, NHWC (C contiguous)
//   out: [32, 128] f32
// Pure HBM-streaming reduction: 822 MB read, 16 KB written.
//
// Trend probe: occ 2 (128-reg budget), UNROLL 16 front-batched streaming
// LDG.128 folded into 8 accumulators (~100 live regs, no staging).
// 16 warps/SM x 16 loads = 256 in flight per SM with HALF the CTAs
// contending in the L1tex wavefront queue vs occ 4. Grid (37, 32) strided
// rows = ~3.9 waves at occ 2 for fine tail backfill.
// Fallback: R11 config (occ3/UNROLL12) banked at 118.8us / 88.9% DRAM.

static constexpr int B  = 32;
static constexpr int HW = 224 * 224;   // 50176 spatial rows per batch
static constexpr int C  = 128;         // channels (contiguous)
static constexpr int C4 = C / 4;       // 32 float4 groups per row

static constexpr int THREADS = 256;    // 32 c4-lanes x 8 row-lanes
static constexpr int ROWS_PER_BLK = THREADS / C4;       // 8
static constexpr int GRID_X = 37;      // 37*32 = 1184 blocks
static constexpr int STRIDE = GRID_X * ROWS_PER_BLK;    // 296 rows
static constexpr int UNROLL = 16;      // loads front-batched per iteration
static constexpr int NACC   = 8;       // accumulators (fold pairs)

__device__ __forceinline__ float4 f4max(float4 a, float4 b) {
    return make_float4(fmaxf(a.x, b.x), fmaxf(a.y, b.y),
                       fmaxf(a.z, b.z), fmaxf(a.w, b.w));
}

// Float atomic-max via monotone int/uint reinterpretation (init = -FLT_MAX).
__device__ __forceinline__ void atomicMaxF(float* addr, float v) {
    if (v >= 0.0f) {
        atomicMax(reinterpret_cast<int*>(addr), __float_as_int(v));
    } else {
        atomicMin(reinterpret_cast<unsigned int*>(addr), __float_as_uint(v));
    }
}

__global__ void init_out_kernel(float* __restrict__ out, int n) {
    int i = blockIdx.x * blockDim.x + threadIdx.x;
    if (i < n) out[i] = -FLT_MAX;
}

__global__ __launch_bounds__(THREADS, 2)   // 128-reg budget: 16-load batch
void max_spatial_kernel(const float* __restrict__ in, float* __restrict__ out) {
    const int b   = blockIdx.y;
    const int c4  = threadIdx.x & (C4 - 1);   // float4 channel group 0..31
    const int r   = threadIdx.x >> 5;         // row lane 0..7

    // Base pointer for this batch + channel group (float4 units)
    const float4* base =
        reinterpret_cast<const float4*>(in + (size_t)b * HW * C) + c4;

    int row = blockIdx.x * ROWS_PER_BLK + r;

    float4 m[NACC];
    #pragma unroll
    for (int i = 0; i < NACC; i++)
        m[i] = make_float4(-FLT_MAX, -FLT_MAX, -FLT_MAX, -FLT_MAX);

    // 16 independent streaming LDG.128 front-batched per iteration.
    for (; row + (UNROLL - 1) * STRIDE < HW; row += UNROLL * STRIDE) {
        float4 v[UNROLL];
        #pragma unroll
        for (int i = 0; i < UNROLL; i++)
            v[i] = __ldcs(base + (size_t)(row + i * STRIDE) * C4);
        #pragma unroll
        for (int i = 0; i < NACC; i++)
            m[i] = f4max(m[i], f4max(v[2 * i], v[2 * i + 1]));
    }
    for (; row < HW; row += STRIDE) {
        m[0] = f4max(m[0], __ldcs(base + (size_t)row * C4));
    }

    // Tree-combine the 8 accumulators
    #pragma unroll
    for (int s = NACC / 2; s > 0; s >>= 1)
        #pragma unroll
        for (int i = 0; i < s; i++)
            m[i] = f4max(m[i], m[i + s]);

    // Reduce across the 8 row-lanes sharing this c4 (tid, tid+32, ... tid+224)
    __shared__ float4 sm[THREADS];
    sm[threadIdx.x] = m[0];
    __syncthreads();
    if (threadIdx.x < 128) sm[threadIdx.x] = f4max(sm[threadIdx.x], sm[threadIdx.x + 128]);
    __syncthreads();
    if (threadIdx.x < 64)  sm[threadIdx.x] = f4max(sm[threadIdx.x], sm[threadIdx.x + 64]);
    __syncthreads();
    if (threadIdx.x < 32) {
        float4 v = f4max(sm[threadIdx.x], sm[threadIdx.x + 32]);
        float* o = out + b * C + threadIdx.x * 4;
        atomicMaxF(o + 0, v.x);
        atomicMaxF(o + 1, v.y);
        atomicMaxF(o + 2, v.z);
        atomicMaxF(o + 3, v.w);
    }
}

extern "C" void kernel_launch(void* const* d_in, const int* in_sizes, int n_in,
                              void* d_out, int out_size) {
    const float* in = (const float*)d_in[0];
    float* out = (float*)d_out;

    init_out_kernel<<<(out_size + 255) / 256, 256>>>(out, out_size);

    dim3 grid(GRID_X, B);
    max_spatial_kernel<<<grid, THREADS>>>(in, out);
}

// round 13
// speedup vs baseline: 1.0480x; 1.0480x over previous
#include <cuda_runtime.h>
#include <cuda_bf16.h>
#include <float.h>

// Problem: out[b][c] = max over (h,w) of in[b][h][w][c]
//   in : [32, 224, 224, 128] f32, NHWC (C contiguous)
//   out: [32, 128] f32
// Pure HBM-streaming reduction: 822 MB read, 16 KB written.
//
// FINAL configuration (converged over 13 rounds, best = 118.8us @ 88.9%
// DRAM / 7.04 TB/s): grid (37, 32) strided rows, occ 3 (80 regs) so 12
// streaming LDG.128 are front-batched per thread, folded into 6
// accumulators. smem tree reduce + float atomicMax into a
// -FLT_MAX-initialized output.
//
// Convergence evidence: occ {2,3,4} x MLP {4..16} x grid {608..1216} x
// {strided, contiguous} x {atomics, last-block-combine} all measure
// 6.6-7.0 TB/s; identical-source re-benches vary +-2.5us. occ 2 loses
// (warp-eligibility gaps + coarse tail), occ 4 caps regs at 64 (load
// staging). 822 MB at the ~7.0 TB/s practical ceiling = ~117.5us floor;
// this kernel measures 117-120us.

static constexpr int B  = 32;
static constexpr int HW = 224 * 224;   // 50176 spatial rows per batch
static constexpr int C  = 128;         // channels (contiguous)
static constexpr int C4 = C / 4;       // 32 float4 groups per row

static constexpr int THREADS = 256;    // 32 c4-lanes x 8 row-lanes
static constexpr int ROWS_PER_BLK = THREADS / C4;       // 8
static constexpr int GRID_X = 37;      // 37*32 = 1184 blocks
static constexpr int STRIDE = GRID_X * ROWS_PER_BLK;    // 296 rows
static constexpr int UNROLL = 12;      // loads front-batched per iteration
static constexpr int NACC   = 6;       // accumulators (fold pairs)

__device__ __forceinline__ float4 f4max(float4 a, float4 b) {
    return make_float4(fmaxf(a.x, b.x), fmaxf(a.y, b.y),
                       fmaxf(a.z, b.z), fmaxf(a.w, b.w));
}

// Float atomic-max via monotone int/uint reinterpretation (init = -FLT_MAX).
__device__ __forceinline__ void atomicMaxF(float* addr, float v) {
    if (v >= 0.0f) {
        atomicMax(reinterpret_cast<int*>(addr), __float_as_int(v));
    } else {
        atomicMin(reinterpret_cast<unsigned int*>(addr), __float_as_uint(v));
    }
}

__global__ void init_out_kernel(float* __restrict__ out, int n) {
    int i = blockIdx.x * blockDim.x + threadIdx.x;
    if (i < n) out[i] = -FLT_MAX;
}

__global__ __launch_bounds__(THREADS, 3)   // 80 regs: full 12-load batch
void max_spatial_kernel(const float* __restrict__ in, float* __restrict__ out) {
    const int b   = blockIdx.y;
    const int c4  = threadIdx.x & (C4 - 1);   // float4 channel group 0..31
    const int r   = threadIdx.x >> 5;         // row lane 0..7

    // Base pointer for this batch + channel group (float4 units)
    const float4* base =
        reinterpret_cast<const float4*>(in + (size_t)b * HW * C) + c4;

    int row = blockIdx.x * ROWS_PER_BLK + r;

    float4 m[NACC];
    #pragma unroll
    for (int i = 0; i < NACC; i++)
        m[i] = make_float4(-FLT_MAX, -FLT_MAX, -FLT_MAX, -FLT_MAX);

    // 12 independent streaming LDG.128 front-batched per iteration.
    for (; row + (UNROLL - 1) * STRIDE < HW; row += UNROLL * STRIDE) {
        float4 v[UNROLL];
        #pragma unroll
        for (int i = 0; i < UNROLL; i++)
            v[i] = __ldcs(base + (size_t)(row + i * STRIDE) * C4);
        #pragma unroll
        for (int i = 0; i < NACC; i++)
            m[i] = f4max(m[i], f4max(v[2 * i], v[2 * i + 1]));
    }
    for (; row < HW; row += STRIDE) {
        m[0] = f4max(m[0], __ldcs(base + (size_t)row * C4));
    }

    // Combine the 6 accumulators
    m[0] = f4max(m[0], m[1]);
    m[2] = f4max(m[2], m[3]);
    m[4] = f4max(m[4], m[5]);
    m[0] = f4max(m[0], f4max(m[2], m[4]));

    // Reduce across the 8 row-lanes sharing this c4 (tid, tid+32, ... tid+224)
    __shared__ float4 sm[THREADS];
    sm[threadIdx.x] = m[0];
    __syncthreads();
    if (threadIdx.x < 128) sm[threadIdx.x] = f4max(sm[threadIdx.x], sm[threadIdx.x + 128]);
    __syncthreads();
    if (threadIdx.x < 64)  sm[threadIdx.x] = f4max(sm[threadIdx.x], sm[threadIdx.x + 64]);
    __syncthreads();
    if (threadIdx.x < 32) {
        float4 v = f4max(sm[threadIdx.x], sm[threadIdx.x + 32]);
        float* o = out + b * C + threadIdx.x * 4;
        atomicMaxF(o + 0, v.x);
        atomicMaxF(o + 1, v.y);
        atomicMaxF(o + 2, v.z);
        atomicMaxF(o + 3, v.w);
    }
}

extern "C" void kernel_launch(void* const* d_in, const int* in_sizes, int n_in,
                              void* d_out, int out_size) {
    const float* in = (const float*)d_in[0];
    float* out = (float*)d_out;

    init_out_kernel<<<(out_size + 255) / 256, 256>>>(out, out_size);

    dim3 grid(GRID_X, B);
    max_spatial_kernel<<<grid, THREADS>>>(in, out);
}